// round 16
// baseline (speedup 1.0000x reference)
#include <cuda_runtime.h>

// Quanvolution (4-qubit, 3 layers) + linear head + log_softmax — ONE fused kernel.
// 512 blocks x 224 threads: one IMAGE PAIR per block.
//   Phase 1: threads 0..195 each simulate one packed (imageA,imageB) patch (R7 math).
//   Phase 2: all 224 threads do the GEMV head on shared feats + log_softmax.
// __launch_bounds__(224,3) => 97-reg cap (natural need: 96) => 3 blocks/SM, 21 warps.
// d_in[0]=x (1024*784 f32), d_in[1]=q_params (3*4*3), d_in[2]=W (10*784), d_in[3]=b (10)
// d_out = log_softmax logits (1024*10 f32)

#define NT 224

struct pf2 { unsigned long long v; };

__device__ __forceinline__ pf2 ppack(float lo, float hi) {
    pf2 r; asm("mov.b64 %0, {%1, %2};" : "=l"(r.v) : "f"(lo), "f"(hi)); return r;
}
__device__ __forceinline__ pf2 psplat(float x_) {
    pf2 r; asm("mov.b64 %0, {%1, %1};" : "=l"(r.v) : "f"(x_)); return r;
}
__device__ __forceinline__ void punpack(pf2 a, float& lo, float& hi) {
    asm("mov.b64 {%0, %1}, %2;" : "=f"(lo), "=f"(hi) : "l"(a.v));
}
__device__ __forceinline__ pf2 pmul(pf2 a, pf2 b) {
    pf2 r; asm("mul.rn.f32x2 %0, %1, %2;" : "=l"(r.v) : "l"(a.v), "l"(b.v)); return r;
}
__device__ __forceinline__ pf2 padd(pf2 a, pf2 b) {
    pf2 r; asm("add.rn.f32x2 %0, %1, %2;" : "=l"(r.v) : "l"(a.v), "l"(b.v)); return r;
}
__device__ __forceinline__ pf2 pfma(pf2 a, pf2 b, pf2 c) {
    pf2 r; asm("fma.rn.f32x2 %0, %1, %2, %3;" : "=l"(r.v) : "l"(a.v), "l"(b.v), "l"(c.v)); return r;
}
__device__ __forceinline__ pf2 pneg(pf2 a) { pf2 r; r.v = a.v ^ 0x8000000080000000ULL; return r; }
__device__ __forceinline__ pf2 pzero() { pf2 r; r.v = 0ULL; return r; }

// CNOT ring 0->1,1->2,2->3,3->0 as a composite index permutation (wire w = bit 3-w).
__device__ __forceinline__ int qperm(int b) {
    int c = b ^ ((b & 1) ? 8 : 0);
    int d = c ^ ((c & 2) ? 1 : 0);
    int e = d ^ ((d & 4) ? 2 : 0);
    return e ^ ((e & 8) ? 4 : 0);
}

__device__ __forceinline__ void apply_su2(pf2* sx, pf2* sy, int m,
                                          pf2 gx, pf2 gy, pf2 dx, pf2 dy) {
    pf2 ngy = pneg(gy), ndx = pneg(dx), ndy = pneg(dy);
#pragma unroll
    for (int i = 0; i < 16; i++) {
        if (!(i & m)) {
            int j = i | m;
            pf2 ax = sx[i], ay = sy[i], bx = sx[j], by = sy[j];
            pf2 nx = pmul(gx, ax); nx = pfma(ngy, ay, nx); nx = pfma(dx, bx, nx); nx = pfma(ndy, by, nx);
            pf2 ny = pmul(gx, ay); ny = pfma(gy, ax, ny); ny = pfma(dx, by, ny); ny = pfma(dy, bx, ny);
            pf2 mx = pmul(ndx, ax); mx = pfma(ndy, ay, mx); mx = pfma(gx, bx, mx); mx = pfma(gy, by, mx);
            pf2 my = pmul(ndx, ay); my = pfma(dy, ax, my); my = pfma(gx, by, my); my = pfma(ngy, bx, my);
            sx[i] = nx; sy[i] = ny; sx[j] = mx; sy[j] = my;
        }
    }
}

// V = RY(c,s) * U  with U = [[a,b],[-b*,a*]] stored splat in shared.
__device__ __forceinline__ void build_v(pf2 c, pf2 s, const float* U,
                                        pf2& gx, pf2& gy, pf2& dx, pf2& dy) {
    pf2 uax = psplat(U[0]), uay = psplat(U[1]), ubx = psplat(U[2]), uby = psplat(U[3]);
    gx = pfma(c, uax, pmul(s, ubx));
    gy = pfma(c, uay, pneg(pmul(s, uby)));
    dx = pfma(c, ubx, pneg(pmul(s, uax)));
    dy = pfma(c, uby, pmul(s, uay));
}

__device__ __forceinline__ void cnot_sw(pf2* sx, pf2* sy, int mc, int mt) {
#pragma unroll
    for (int i = 0; i < 16; i++) {
        if ((i & mc) && !(i & mt)) {
            int j = i | mt;
            pf2 t = sx[i]; sx[i] = sx[j]; sx[j] = t;
            t = sy[i]; sy[i] = sy[j]; sy[j] = t;
        }
    }
}

__global__ void __launch_bounds__(NT, 3)
quanv_fused(const float* __restrict__ x, const float* __restrict__ qp,
            const float* __restrict__ W, const float* __restrict__ bias,
            float* __restrict__ out) {
    __shared__ float Um[12][8];                // ax, ay, bx, by, D, EX, EYn, EYp
    __shared__ unsigned long long feats[784];  // packed (featA, featB)
    __shared__ unsigned long long red[7][10];  // per-warp partial logits

    const int t = threadIdx.x;
    const int ip = blockIdx.x;                 // image pair 0..511

    if (t < 12) {
        float a  = 0.5f * qp[t * 3 + 0];
        float be = 0.5f * qp[t * 3 + 1];
        float g  = 0.5f * qp[t * 3 + 2];
        float cp, sp, cm, sm, cb, sb;
        sincosf(a + g, &sp, &cp);
        sincosf(a - g, &sm, &cm);
        sincosf(be, &sb, &cb);
        float ax = cb * cp, ay = -cb * sp, bx = -sb * cm, by = -sb * sm;
        Um[t][0] = ax; Um[t][1] = ay; Um[t][2] = bx; Um[t][3] = by;
        Um[t][4] = ax * ax + ay * ay - bx * bx - by * by;   // D
        float reab = ax * bx + ay * by;
        float imab = ax * by - ay * bx;
        Um[t][5] =  4.0f * reab;    // EX
        Um[t][6] = -4.0f * imab;    // coeff sx_i*sy_j
        Um[t][7] =  4.0f * imab;    // coeff sy_i*sx_j
    }
    __syncthreads();

    if (t < 196) {
        const int pr = t / 14;
        const int pc = t - pr * 14;
        const float* xA = x + (size_t)ip * 1568;
        const float* xB = xA + 784;
        const int i0 = pr * 56 + pc * 2;

        pf2 cw[4], sw[4];
        {
            float thA[4] = { xA[i0], xA[i0 + 1], xA[i0 + 28], xA[i0 + 29] };
            float thB[4] = { xB[i0], xB[i0 + 1], xB[i0 + 28], xB[i0 + 29] };
#pragma unroll
            for (int w = 0; w < 4; w++) {
                float cA, sA, cB, sB;
                __sincosf(0.5f * thA[w], &sA, &cA);
                __sincosf(0.5f * thB[w], &sB, &cB);
                cw[w] = ppack(cA, cB);
                sw[w] = ppack(sA, sB);
            }
        }

        // Layer-0 RY product state with the first CNOT ring folded in as permutation.
        pf2 sx[16], sy[16];
        {
            pf2 p01[4], p23[4];
            p01[0] = pmul(cw[0], cw[1]); p01[1] = pmul(cw[0], sw[1]);
            p01[2] = pmul(sw[0], cw[1]); p01[3] = pmul(sw[0], sw[1]);
            p23[0] = pmul(cw[2], cw[3]); p23[1] = pmul(cw[2], sw[3]);
            p23[2] = pmul(sw[2], cw[3]); p23[3] = pmul(sw[2], sw[3]);
#pragma unroll
            for (int i = 0; i < 16; i++) {
                int q = qperm(i);
                sx[i] = pmul(p01[q >> 2], p23[q & 3]);
            }
        }

        // V0 = RY1 * U0; wire 0 specialized on the purely-real state.
        {
            pf2 gx, gy, dx, dy;
            build_v(cw[0], sw[0], Um[0], gx, gy, dx, dy);
            pf2 ndx = pneg(dx), ngy = pneg(gy);
#pragma unroll
            for (int i = 0; i < 8; i++) {
                int j = i | 8;
                pf2 a = sx[i], bb = sx[j];
                sx[i] = pfma(gx, a, pmul(dx, bb));
                sy[i] = pfma(gy, a, pmul(dy, bb));
                sx[j] = pfma(ndx, a, pmul(gx, bb));
                sy[j] = pfma(dy, a, pmul(ngy, bb));
            }
        }
#pragma unroll
        for (int w = 1; w < 4; w++) {
            pf2 gx, gy, dx, dy;
            build_v(cw[w], sw[w], Um[w], gx, gy, dx, dy);
            apply_su2(sx, sy, 8 >> w, gx, gy, dx, dy);
        }
        cnot_sw(sx, sy, 8, 4); cnot_sw(sx, sy, 4, 2);
        cnot_sw(sx, sy, 2, 1); cnot_sw(sx, sy, 1, 8);

        // V1 = RY2 * U1
#pragma unroll
        for (int w = 0; w < 4; w++) {
            pf2 gx, gy, dx, dy;
            build_v(cw[w], sw[w], Um[4 + w], gx, gy, dx, dy);
            apply_su2(sx, sy, 8 >> w, gx, gy, dx, dy);
        }
        cnot_sw(sx, sy, 8, 4); cnot_sw(sx, sy, 4, 2);
        cnot_sw(sx, sy, 2, 1); cnot_sw(sx, sy, 1, 8);

        // Final layer U2 folded into expectations: <Z_w> via M = U2^dag Z U2.
#pragma unroll
        for (int w = 0; w < 4; w++) {
            const float* U2 = Um[8 + w];
            pf2 sD  = psplat(U2[4]);
            pf2 snD = pneg(sD);
            pf2 sEX = psplat(U2[5]);
            pf2 sEn = psplat(U2[6]);
            pf2 sEp = psplat(U2[7]);
            const int m = 8 >> w;
            pf2 acc = pzero();
#pragma unroll
            for (int i = 0; i < 16; i++) {
                if (!(i & m)) {
                    int j = i | m;
                    pf2 pi = pfma(sx[i], sx[i], pmul(sy[i], sy[i]));
                    pf2 pj = pfma(sx[j], sx[j], pmul(sy[j], sy[j]));
                    acc = pfma(sD, pi, acc);
                    acc = pfma(snD, pj, acc);
                    pf2 rec = pfma(sx[i], sx[j], pmul(sy[i], sy[j]));
                    acc = pfma(sEX, rec, acc);
                    acc = pfma(sEn, pmul(sx[i], sy[j]), acc);
                    acc = pfma(sEp, pmul(sy[i], sx[j]), acc);
                }
            }
            feats[t * 4 + w] = acc.v;
        }
    }
    __syncthreads();

    // ---- Phase 2: packed logits for both images (all 224 threads) ----
    pf2 acc[10];
#pragma unroll
    for (int c = 0; c < 10; c++) acc[c] = pzero();

    for (int j = t; j < 784; j += NT) {
        pf2 fv; fv.v = feats[j];
#pragma unroll
        for (int c = 0; c < 10; c++)
            acc[c] = pfma(fv, psplat(W[c * 784 + j]), acc[c]);
    }

#pragma unroll
    for (int c = 0; c < 10; c++) {
#pragma unroll
        for (int off = 16; off > 0; off >>= 1) {
            pf2 o; o.v = __shfl_xor_sync(0xffffffffu, acc[c].v, off);
            acc[c] = padd(acc[c], o);
        }
        if ((t & 31) == 0) red[t >> 5][c] = acc[c].v;
    }
    __syncthreads();

    if (t < 2) {
        float l[10];
        float mx = -1e30f;
#pragma unroll
        for (int c = 0; c < 10; c++) {
            float s = bias[c];
#pragma unroll
            for (int wg = 0; wg < 7; wg++) {
                pf2 r; r.v = red[wg][c];
                float lo, hi; punpack(r, lo, hi);
                s += (t == 0) ? lo : hi;
            }
            l[c] = s;
            mx = fmaxf(mx, s);
        }
        float sum = 0.0f;
#pragma unroll
        for (int c = 0; c < 10; c++) sum += expf(l[c] - mx);
        float lse = logf(sum);
#pragma unroll
        for (int c = 0; c < 10; c++) out[(2 * ip + t) * 10 + c] = l[c] - mx - lse;
    }
}

extern "C" void kernel_launch(void* const* d_in, const int* in_sizes, int n_in,
                              void* d_out, int out_size) {
    const float* x    = (const float*)d_in[0];
    const float* qp   = (const float*)d_in[1];
    const float* W    = (const float*)d_in[2];
    const float* bias = (const float*)d_in[3];
    float* out = (float*)d_out;

    quanv_fused<<<512, NT>>>(x, qp, W, bias, out);
}

// round 17
// speedup vs baseline: 1.1635x; 1.1635x over previous
#include <cuda_runtime.h>

// Quanvolution (4-qubit, 3 layers) + linear head + log_softmax.
// K1: 1568 blocks x 128 threads — ONE image-patch sim per thread, SCALAR fp32.
//     (Packing to f32x2 cost 96 regs -> 20 warps/SM and only 1.33x pipe due to
//      FFMA2 rt=3 banking; scalar halves state regs -> more warps, rt=2.)
// K2: 1024 blocks x 256 threads, one block per image (GEMV head + log_softmax).
// d_in[0]=x (1024*784 f32), d_in[1]=q_params (3*4*3), d_in[2]=W (10*784), d_in[3]=b (10)
// d_out = log_softmax logits (1024*10 f32)

// CNOT ring 0->1,1->2,2->3,3->0 as a composite index permutation (wire w = bit 3-w).
__device__ __forceinline__ int qperm(int b) {
    int c = b ^ ((b & 1) ? 8 : 0);
    int d = c ^ ((c & 2) ? 1 : 0);
    int e = d ^ ((d & 4) ? 2 : 0);
    return e ^ ((e & 8) ? 4 : 0);
}

// General SU(2) gate [[g, d],[-d*, g*]] on wire mask m (scalar complex).
__device__ __forceinline__ void apply_su2(float* sx, float* sy, int m,
                                          float gx, float gy, float dx, float dy) {
#pragma unroll
    for (int i = 0; i < 16; i++) {
        if (!(i & m)) {
            int j = i | m;
            float ax = sx[i], ay = sy[i], bx = sx[j], by = sy[j];
            float nx =  gx * ax; nx = fmaf(-gy, ay, nx); nx = fmaf(dx, bx, nx); nx = fmaf(-dy, by, nx);
            float ny =  gx * ay; ny = fmaf( gy, ax, ny); ny = fmaf(dx, by, ny); ny = fmaf( dy, bx, ny);
            float mx = -dx * ax; mx = fmaf(-dy, ay, mx); mx = fmaf(gx, bx, mx); mx = fmaf( gy, by, mx);
            float my = -dx * ay; my = fmaf( dy, ax, my); my = fmaf(gx, by, my); my = fmaf(-gy, bx, my);
            sx[i] = nx; sy[i] = ny; sx[j] = mx; sy[j] = my;
        }
    }
}

// V = RY(c,s) * U with U = [[a,b],[-b*,a*]] (from shared).
__device__ __forceinline__ void build_v(float c, float s, const float* U,
                                        float& gx, float& gy, float& dx, float& dy) {
    gx = fmaf(c, U[0],  s * U[2]);
    gy = fmaf(c, U[1], -s * U[3]);
    dx = fmaf(c, U[2], -s * U[0]);
    dy = fmaf(c, U[3],  s * U[1]);
}

__device__ __forceinline__ void cnot_sw(float* sx, float* sy, int mc, int mt) {
#pragma unroll
    for (int i = 0; i < 16; i++) {
        if ((i & mc) && !(i & mt)) {
            int j = i | mt;
            float t = sx[i]; sx[i] = sx[j]; sx[j] = t;
            t = sy[i]; sy[i] = sy[j]; sy[j] = t;
        }
    }
}

// Scalar features, image-major: [1024 images][784 features].
__device__ float g_feats[1024 * 784];

__global__ void __launch_bounds__(128)
quanv_k1(const float* __restrict__ x, const float* __restrict__ qp) {
    __shared__ float Um[12][8];  // ax, ay, bx, by, D, EX, EYn, EYp

    const int t = threadIdx.x;
    if (t < 12) {
        float a  = 0.5f * qp[t * 3 + 0];
        float be = 0.5f * qp[t * 3 + 1];
        float g  = 0.5f * qp[t * 3 + 2];
        float cp, sp, cm, sm, cb, sb;
        sincosf(a + g, &sp, &cp);
        sincosf(a - g, &sm, &cm);
        sincosf(be, &sb, &cb);
        float ax = cb * cp, ay = -cb * sp, bx = -sb * cm, by = -sb * sm;
        Um[t][0] = ax; Um[t][1] = ay; Um[t][2] = bx; Um[t][3] = by;
        Um[t][4] = ax * ax + ay * ay - bx * bx - by * by;   // D
        float reab = ax * bx + ay * by;
        float imab = ax * by - ay * bx;
        Um[t][5] =  4.0f * reab;    // EX
        Um[t][6] = -4.0f * imab;    // coeff sx_i*sy_j
        Um[t][7] =  4.0f * imab;    // coeff sy_i*sx_j
    }
    __syncthreads();

    const int g = blockIdx.x * 128 + t;        // 0..200703, exact
    const int img = g / 196;                   // image 0..1023
    const int patch = g - img * 196;
    const int pr = patch / 14;
    const int pc = patch - pr * 14;
    const float* xi = x + (size_t)img * 784;
    const int i0 = pr * 56 + pc * 2;

    float cw[4], sw[4];
    {
        float th[4] = { xi[i0], xi[i0 + 1], xi[i0 + 28], xi[i0 + 29] };
#pragma unroll
        for (int w = 0; w < 4; w++)
            __sincosf(0.5f * th[w], &sw[w], &cw[w]);
    }

    // Layer-0 RY product state with the first CNOT ring folded in as permutation.
    float sx[16], sy[16];
    {
        float p01[4], p23[4];
        p01[0] = cw[0] * cw[1]; p01[1] = cw[0] * sw[1];
        p01[2] = sw[0] * cw[1]; p01[3] = sw[0] * sw[1];
        p23[0] = cw[2] * cw[3]; p23[1] = cw[2] * sw[3];
        p23[2] = sw[2] * cw[3]; p23[3] = sw[2] * sw[3];
#pragma unroll
        for (int i = 0; i < 16; i++) {
            int q = qperm(i);
            sx[i] = p01[q >> 2] * p23[q & 3];
        }
    }

    // V0 = RY1 * U0; wire 0 specialized on the purely-real state.
    {
        float gx, gy, dx, dy;
        build_v(cw[0], sw[0], Um[0], gx, gy, dx, dy);
#pragma unroll
        for (int i = 0; i < 8; i++) {
            int j = i | 8;
            float a = sx[i], b = sx[j];
            sx[i] = fmaf(gx, a,  dx * b);
            sy[i] = fmaf(gy, a,  dy * b);
            sx[j] = fmaf(-dx, a, gx * b);
            sy[j] = fmaf(dy, a, -gy * b);
        }
    }
#pragma unroll
    for (int w = 1; w < 4; w++) {
        float gx, gy, dx, dy;
        build_v(cw[w], sw[w], Um[w], gx, gy, dx, dy);
        apply_su2(sx, sy, 8 >> w, gx, gy, dx, dy);
    }
    cnot_sw(sx, sy, 8, 4); cnot_sw(sx, sy, 4, 2);
    cnot_sw(sx, sy, 2, 1); cnot_sw(sx, sy, 1, 8);

    // V1 = RY2 * U1
#pragma unroll
    for (int w = 0; w < 4; w++) {
        float gx, gy, dx, dy;
        build_v(cw[w], sw[w], Um[4 + w], gx, gy, dx, dy);
        apply_su2(sx, sy, 8 >> w, gx, gy, dx, dy);
    }
    cnot_sw(sx, sy, 8, 4); cnot_sw(sx, sy, 4, 2);
    cnot_sw(sx, sy, 2, 1); cnot_sw(sx, sy, 1, 8);

    // Final layer U2 folded into expectations: <Z_w> via M = U2^dag Z U2.
    float* dst = g_feats + (size_t)img * 784 + patch * 4;
#pragma unroll
    for (int w = 0; w < 4; w++) {
        const float* U2 = Um[8 + w];
        const float sD = U2[4], sEX = U2[5], sEn = U2[6], sEp = U2[7];
        const int m = 8 >> w;
        float acc = 0.0f;
#pragma unroll
        for (int i = 0; i < 16; i++) {
            if (!(i & m)) {
                int j = i | m;
                float pi = fmaf(sx[i], sx[i], sy[i] * sy[i]);
                float pj = fmaf(sx[j], sx[j], sy[j] * sy[j]);
                acc = fmaf(sD, pi, acc);
                acc = fmaf(-sD, pj, acc);
                float rec = fmaf(sx[i], sx[j], sy[i] * sy[j]);
                acc = fmaf(sEX, rec, acc);
                acc = fmaf(sEn, sx[i] * sy[j], acc);
                acc = fmaf(sEp, sy[i] * sx[j], acc);
            }
        }
        dst[w] = acc;
    }
}

// K2: one block per image. 1024 blocks x 256 threads, contiguous feat loads.
__global__ void __launch_bounds__(256)
head_k2(const float* __restrict__ W, const float* __restrict__ bias,
        float* __restrict__ out) {
    __shared__ float red[8][10];

    const int t = threadIdx.x;
    const int img = blockIdx.x;                // 0..1023
    const float* f = g_feats + (size_t)img * 784;

    float acc[10];
#pragma unroll
    for (int c = 0; c < 10; c++) acc[c] = 0.0f;

#pragma unroll
    for (int k = 0; k < 4; k++) {
        int j = t + k * 256;
        if (j < 784) {
            float fv = f[j];
#pragma unroll
            for (int c = 0; c < 10; c++)
                acc[c] = fmaf(fv, W[c * 784 + j], acc[c]);
        }
    }

#pragma unroll
    for (int c = 0; c < 10; c++) {
        float v = acc[c];
#pragma unroll
        for (int off = 16; off > 0; off >>= 1)
            v += __shfl_xor_sync(0xffffffffu, v, off);
        if ((t & 31) == 0) red[t >> 5][c] = v;
    }
    __syncthreads();

    if (t == 0) {
        float l[10];
        float mx = -1e30f;
#pragma unroll
        for (int c = 0; c < 10; c++) {
            float s = bias[c];
#pragma unroll
            for (int wg = 0; wg < 8; wg++) s += red[wg][c];
            l[c] = s;
            mx = fmaxf(mx, s);
        }
        float sum = 0.0f;
#pragma unroll
        for (int c = 0; c < 10; c++) sum += expf(l[c] - mx);
        float lse = logf(sum);
#pragma unroll
        for (int c = 0; c < 10; c++) out[img * 10 + c] = l[c] - mx - lse;
    }
}

extern "C" void kernel_launch(void* const* d_in, const int* in_sizes, int n_in,
                              void* d_out, int out_size) {
    const float* x    = (const float*)d_in[0];
    const float* qp   = (const float*)d_in[1];
    const float* W    = (const float*)d_in[2];
    const float* bias = (const float*)d_in[3];
    float* out = (float*)d_out;

    quanv_k1<<<1568, 128>>>(x, qp);
    head_k2<<<1024, 256>>>(W, bias, out);
}